// round 9
// baseline (speedup 1.0000x reference)
#include <cuda_runtime.h>
#include <cuda_fp16.h>
#include <cstdint>
#include <cstddef>

#define B_N   8
#define C_IN  64
#define C_OUT 64
#define HW    256
#define KS    31
#define NCH   16                // channels per chunk (K=16 per mma)
#define NCC   4                 // 4 channel chunks
#define NITER (NCC*KS)          // 124

#define TXT   16
#define TYT   32
#define YPADN 286
#define XPADN 292
#define SLOTS 64                // direct-mapped row slots (rolling offset)
#define ROWU  94                // uint4 per staged row (47 x-positions * 32B)
#define ROWB  (ROWU*16)         // 1504 bytes
#define WBLKB (KS*C_OUT*32)     // 63488 bytes per (cc,u) weight block
#define SM_W_OFF (SLOTS*ROWB)   // 96256
#define SMEM_TOTAL (SM_W_OFF + 2*WBLKB)   // 223232 (< 227KB limit)

// ---------------- device scratch ----------------
// padded fp16 signal, 16 ch interleaved per x as units {c2t,c2t+1,c2t+8,c2t+9}:
// [b][cc][piy][px] -> 2 uint4 (32B)
__device__ uint4 g_sH[(size_t)B_N * NCC * YPADN * XPADN * 2];     // ~85.5 MB
// fp16 weights per iter block i=cc*31+u: [v][o] -> 2 uint4 (32B), same interleave
__device__ uint4 g_wH[(size_t)NITER * KS * C_OUT * 2];            // ~7.9 MB

__device__ __forceinline__ uint32_t smem_u32(const void* p) {
    uint32_t a;
    asm("{ .reg .u64 t; cvta.to.shared.u64 t, %1; cvt.u32.u64 %0, t; }" : "=r"(a) : "l"(p));
    return a;
}
__device__ __forceinline__ void cpa16(uint32_t dst, const void* src) {
    asm volatile("cp.async.cg.shared.global [%0], [%1], 16;" :: "r"(dst), "l"(src));
}
__device__ __forceinline__ void cpa_commit() { asm volatile("cp.async.commit_group;"); }
__device__ __forceinline__ void cpa_wait0()  { asm volatile("cp.async.wait_group 0;"); }

__device__ __forceinline__ void hmma16(float* acc, uint32_t a0, uint32_t a1,
                                       uint32_t a2, uint32_t a3,
                                       uint32_t b0, uint32_t b1) {
    asm volatile(
        "mma.sync.aligned.m16n8k16.row.col.f32.f16.f16.f32 "
        "{%0,%1,%2,%3}, {%4,%5,%6,%7}, {%8,%9}, {%0,%1,%2,%3};"
        : "+f"(acc[0]), "+f"(acc[1]), "+f"(acc[2]), "+f"(acc[3])
        : "r"(a0), "r"(a1), "r"(a2), "r"(a3), "r"(b0), "r"(b1));
}

// ---------------- pre-pass: pad + fp16 + interleave signal ----------------
__global__ void prep_sig(const float* __restrict__ sig) {
    size_t idx = (size_t)blockIdx.x * 256 + threadIdx.x;
    const size_t total = (size_t)B_N * NCC * YPADN * XPADN;
    if (idx >= total) return;
    int px  = (int)(idx % XPADN); size_t t = idx / XPADN;
    int piy = (int)(t % YPADN);   t /= YPADN;
    int cc  = (int)(t & 3);       int b = (int)(t >> 2);
    int y = piy - 15, x = px - 16;
    __half h[16];
    #pragma unroll
    for (int k = 0; k < 16; k++) h[k] = __float2half_rn(0.f);
    if ((unsigned)y < HW && (unsigned)x < HW) {
        const float* s = sig + (((size_t)(b * C_IN + cc * NCH) * HW + y) * HW + x);
        #pragma unroll
        for (int k = 0; k < 16; k++)
            h[k] = __float2half_rn(s[(size_t)k * HW * HW]);
    }
    __half o16[16];
    #pragma unroll
    for (int q = 0; q < 4; q++) {
        o16[q*4+0] = h[2*q];   o16[q*4+1] = h[2*q+1];
        o16[q*4+2] = h[2*q+8]; o16[q*4+3] = h[2*q+9];
    }
    const uint4* src = (const uint4*)o16;
    g_sH[idx*2]   = src[0];
    g_sH[idx*2+1] = src[1];
}

// ---------------- pre-pass: transpose + fp16 + interleave weights ----------
__global__ void prep_w(const float* __restrict__ w) {
    size_t idx = (size_t)blockIdx.x * 256 + threadIdx.x;
    const size_t total = (size_t)NITER * KS * C_OUT;
    if (idx >= total) return;
    int o = (int)(idx & 63); size_t t = idx >> 6;
    int v = (int)(t % KS);
    int i = (int)(t / KS);          // block = cc*31+u
    int u = i % KS, cc = i / KS;
    __half h[16];
    #pragma unroll
    for (int k = 0; k < 16; k++)
        h[k] = __float2half_rn(w[(((size_t)o * C_IN + cc * NCH + k) * KS + u) * KS + v]);
    __half o16[16];
    #pragma unroll
    for (int q = 0; q < 4; q++) {
        o16[q*4+0] = h[2*q];   o16[q*4+1] = h[2*q+1];
        o16[q*4+2] = h[2*q+8]; o16[q*4+3] = h[2*q+9];
    }
    const uint4* src = (const uint4*)o16;
    g_wH[idx*2]   = src[0];
    g_wH[idx*2+1] = src[1];
}

// ---------------- main conv kernel ----------------
__global__ void __launch_bounds__(256, 1)
conv_kernel(const float* __restrict__ bias, float* __restrict__ out)
{
    extern __shared__ __align__(128) char smem[];
    const uint32_t sb = smem_u32(smem);
    const int x0 = blockIdx.x * TXT;
    const int y0 = blockIdx.y * TYT;
    const int b  = blockIdx.z;
    const int tid  = threadIdx.x;
    const int wrp  = tid >> 5;
    const int lane = tid & 31;
    const int gid  = lane >> 2;
    const int tig  = lane & 3;

    auto stage_weights = [&](int it) {
        const uint4* src = g_wH + (size_t)it * (KS * C_OUT * 2);
        uint32_t dst = sb + SM_W_OFF + (uint32_t)(it & 1) * WBLKB;
        #pragma unroll 4
        for (int t = tid; t < KS * C_OUT * 2; t += 256)   // 3968 uint4
            cpa16(dst + (uint32_t)t * 16, src + t);
    };
    auto stage_row = [&](int slot, int cc_src, int r) {
        const uint4* src = g_sH +
            ((((size_t)(b * NCC + cc_src) * YPADN + (size_t)(y0 + r)) * XPADN) + x0) * 2;
        uint32_t dst = sb + (uint32_t)slot * ROWB;
        if (tid < ROWU)
            cpa16(dst + (uint32_t)tid * 16, src + tid);
    };

    // ---- prologue: rows 0..31 of cc=0 into slots 0..31, weights(0) ----
    for (int t = tid; t < 32 * ROWU; t += 256) {
        int r = t / ROWU, c = t - r * ROWU;
        const uint4* src = g_sH +
            ((((size_t)(b * NCC + 0) * YPADN + (size_t)(y0 + r)) * XPADN) + x0) * 2 + c;
        cpa16(sb + (uint32_t)r * ROWB + (uint32_t)c * 16, src);
    }
    stage_weights(0);
    cpa_commit();

    float acc[4][8][4];
    #pragma unroll
    for (int mi = 0; mi < 4; mi++)
      #pragma unroll
      for (int nf = 0; nf < 8; nf++)
        #pragma unroll
        for (int r = 0; r < 4; r++)
          acc[mi][nf][r] = 0.f;

    cpa_wait0();
    __syncthreads();

    int u = 0, cc = 0, o = 0;
    for (int i = 0; i < NITER; i++) {
        bool last = (i == NITER - 1);
        // ---- uniform per-iter prefetch ----
        if (!last) {
            if (u <= 29) stage_row((u + 32 + o) & 63, cc, u + 32);
            if (cc < NCC - 1) {
                int onx = (o + 62) & 63;        // next chunk's offset
                if (u >= 1 && u <= 28) {
                    stage_row((u - 1 + onx) & 63, cc + 1, u - 1);
                } else if (u == 29) {
                    stage_row((28 + onx) & 63, cc + 1, 28);
                    stage_row((29 + onx) & 63, cc + 1, 29);
                } else if (u == 30) {
                    stage_row((30 + onx) & 63, cc + 1, 30);
                    stage_row((31 + onx) & 63, cc + 1, 31);
                }
            }
            stage_weights(i + 1);
            cpa_commit();
        }

        // ---- compute: register-pipelined v-loop ----
        {
            const char* wb0 = smem + SM_W_OFF + (i & 1) * WBLKB + gid * 32 + tig * 8;
            const char* rowp[4];
            #pragma unroll
            for (int mi = 0; mi < 4; mi++) {
                int s = (wrp * 4 + mi + u + o) & 63;
                rowp[mi] = smem + s * ROWB + tig * 8 + (gid + 1) * 32;
            }

            uint2 cb[8], nb[8];
            uint2 ca0[4], ca1[4], na0[4], na1[4];

            #define LOADB(dst, vv) { \
                const char* wb_ = wb0 + (vv) * 2048; \
                _Pragma("unroll") \
                for (int nf = 0; nf < 8; nf++) \
                    dst[nf] = *(const uint2*)(wb_ + nf * 256); }
            #define LOADA(d0, d1, vv) { \
                _Pragma("unroll") \
                for (int mi = 0; mi < 4; mi++) { \
                    const char* ap_ = rowp[mi] + (vv) * 32; \
                    d0[mi] = *(const uint2*)(ap_); \
                    d1[mi] = *(const uint2*)(ap_ + 256); } }
            #define MMAB(bf, a0, a1) { \
                _Pragma("unroll") \
                for (int nf = 0; nf < 8; nf++) \
                    _Pragma("unroll") \
                    for (int mi = 0; mi < 4; mi++) \
                        hmma16(acc[mi][nf], a0[mi].x, a1[mi].x, a0[mi].y, a1[mi].y, \
                               bf[nf].x, bf[nf].y); }

            LOADB(cb, 0);
            LOADA(ca0, ca1, 0);
            #pragma unroll 1
            for (int v = 0; v < 30; v += 2) {
                LOADB(nb, v + 1);
                LOADA(na0, na1, v + 1);
                MMAB(cb, ca0, ca1);
                LOADB(cb, v + 2);
                LOADA(ca0, ca1, v + 2);
                MMAB(nb, na0, na1);
            }
            MMAB(cb, ca0, ca1);   // v = 30

            #undef LOADB
            #undef LOADA
            #undef MMAB
        }

        // ---- retire prefetch, advance ----
        if (!last) {
            cpa_wait0();
            __syncthreads();
            if (u == 30) { u = 0; cc++; o = (o + 62) & 63; }
            else u++;
        }
    }

    // ---- epilogue ----
    #pragma unroll
    for (int mi = 0; mi < 4; mi++) {
        int y = y0 + wrp * 4 + mi;
        #pragma unroll
        for (int nf = 0; nf < 8; nf++) {
            int on = nf * 8 + tig * 2;
            float bv0 = __ldg(&bias[on]);
            float bv1 = __ldg(&bias[on + 1]);
            int xa = x0 + gid;
            int xb = xa + 8;
            size_t base0 = ((size_t)(b * C_OUT + on) * HW + y) * HW;
            size_t base1 = ((size_t)(b * C_OUT + on + 1) * HW + y) * HW;
            out[base0 + xa] = acc[mi][nf][0] + bv0;
            out[base1 + xa] = acc[mi][nf][1] + bv1;
            out[base0 + xb] = acc[mi][nf][2] + bv0;
            out[base1 + xb] = acc[mi][nf][3] + bv1;
        }
    }
}

// ---------------- launch ----------------
extern "C" void kernel_launch(void* const* d_in, const int* in_sizes, int n_in,
                              void* d_out, int out_size) {
    const float* sig  = (const float*)d_in[0];
    const float* wgt  = (const float*)d_in[1];
    const float* bias = (const float*)d_in[2];
    float* out = (float*)d_out;

    static bool attr_set = false;
    if (!attr_set) {
        cudaFuncSetAttribute(conv_kernel, cudaFuncAttributeMaxDynamicSharedMemorySize,
                             SMEM_TOTAL);
        attr_set = true;
    }

    {
        const size_t total = (size_t)B_N * NCC * YPADN * XPADN;
        prep_sig<<<(unsigned)((total + 255) / 256), 256>>>(sig);
    }
    {
        const size_t total = (size_t)NITER * KS * C_OUT;
        prep_w<<<(unsigned)((total + 255) / 256), 256>>>(wgt);
    }
    dim3 grid(HW / TXT, HW / TYT, B_N);
    conv_kernel<<<grid, 256, SMEM_TOTAL>>>(bias, out);
}

// round 13
// speedup vs baseline: 1.1059x; 1.1059x over previous
#include <cuda_runtime.h>
#include <cuda_fp16.h>
#include <cstdint>
#include <cstddef>

#define B_N   8
#define C_IN  64
#define C_OUT 64
#define HW    256
#define KS    31
#define NCH   16                // channels per chunk (K=16 per mma)
#define NCC   4                 // 4 channel chunks
#define NITER (NCC*KS)          // 124

#define TXT   16
#define TYT   32
#define YPADN 286
#define XPADN 292
#define RSL   33                // ring slots
#define ROWU  94                // uint4 per staged row (47 x-positions * 32B)
#define ROWB  (ROWU*16)         // 1504 bytes
#define WBLKB (KS*C_OUT*32)     // 63488 bytes per (cc,u) weight block
#define SM_W_OFF (RSL*ROWB)     // 49632
#define SMEM_TOTAL (SM_W_OFF + 2*WBLKB)   // 176608

// ---------------- device scratch ----------------
// padded fp16 signal, 16 ch interleaved per x as units {c2t,c2t+1,c2t+8,c2t+9}:
// [b][cc][piy][px] -> 2 uint4 (32B)
__device__ uint4 g_sH[(size_t)B_N * NCC * YPADN * XPADN * 2];     // ~85.5 MB
// fp16 weights, paired-B layout per iter block i=cc*31+u:
// [i][v][p(4)][gid(8)][tig(4)] -> 16B {uint2 o=16p+gid, uint2 o=16p+8+gid}
__device__ uint2 g_wH[(size_t)NITER * KS * 256];                  // ~7.9 MB

__device__ __forceinline__ uint32_t smem_u32(const void* p) {
    uint32_t a;
    asm("{ .reg .u64 t; cvta.to.shared.u64 t, %1; cvt.u32.u64 %0, t; }" : "=r"(a) : "l"(p));
    return a;
}
__device__ __forceinline__ void cpa16(uint32_t dst, const void* src) {
    asm volatile("cp.async.cg.shared.global [%0], [%1], 16;" :: "r"(dst), "l"(src));
}
__device__ __forceinline__ void cpa_commit() { asm volatile("cp.async.commit_group;"); }
__device__ __forceinline__ void cpa_wait0()  { asm volatile("cp.async.wait_group 0;"); }

__device__ __forceinline__ void hmma16(float* acc, uint32_t a0, uint32_t a1,
                                       uint32_t a2, uint32_t a3,
                                       uint32_t b0, uint32_t b1) {
    asm volatile(
        "mma.sync.aligned.m16n8k16.row.col.f32.f16.f16.f32 "
        "{%0,%1,%2,%3}, {%4,%5,%6,%7}, {%8,%9}, {%0,%1,%2,%3};"
        : "+f"(acc[0]), "+f"(acc[1]), "+f"(acc[2]), "+f"(acc[3])
        : "r"(a0), "r"(a1), "r"(a2), "r"(a3), "r"(b0), "r"(b1));
}

// ---------------- pre-pass: pad + fp16 + interleave signal ----------------
__global__ void prep_sig(const float* __restrict__ sig) {
    size_t idx = (size_t)blockIdx.x * 256 + threadIdx.x;
    const size_t total = (size_t)B_N * NCC * YPADN * XPADN;
    if (idx >= total) return;
    int px  = (int)(idx % XPADN); size_t t = idx / XPADN;
    int piy = (int)(t % YPADN);   t /= YPADN;
    int cc  = (int)(t & 3);       int b = (int)(t >> 2);
    int y = piy - 15, x = px - 16;
    __half h[16];
    #pragma unroll
    for (int k = 0; k < 16; k++) h[k] = __float2half_rn(0.f);
    if ((unsigned)y < HW && (unsigned)x < HW) {
        const float* s = sig + (((size_t)(b * C_IN + cc * NCH) * HW + y) * HW + x);
        #pragma unroll
        for (int k = 0; k < 16; k++)
            h[k] = __float2half_rn(s[(size_t)k * HW * HW]);
    }
    __half o16[16];
    #pragma unroll
    for (int q = 0; q < 4; q++) {
        o16[q*4+0] = h[2*q];   o16[q*4+1] = h[2*q+1];
        o16[q*4+2] = h[2*q+8]; o16[q*4+3] = h[2*q+9];
    }
    const uint4* src = (const uint4*)o16;
    g_sH[idx*2]   = src[0];
    g_sH[idx*2+1] = src[1];
}

// ---------------- pre-pass: transpose + fp16 + paired-B weights ----------
// thread per (i, v, o): 16 channels -> 4 uint2 scattered into paired layout
__global__ void prep_w(const float* __restrict__ w) {
    size_t idx = (size_t)blockIdx.x * 256 + threadIdx.x;
    const size_t total = (size_t)NITER * KS * C_OUT;
    if (idx >= total) return;
    int o = (int)(idx & 63); size_t t = idx >> 6;
    int v = (int)(t % KS);
    int i = (int)(t / KS);          // block = cc*31+u
    int u = i % KS, cc = i / KS;
    __half h[16];
    #pragma unroll
    for (int k = 0; k < 16; k++)
        h[k] = __float2half_rn(w[(((size_t)o * C_IN + cc * NCH + k) * KS + u) * KS + v]);
    int gid = o & 7;
    int nf  = o >> 3;
    int p   = nf >> 1;
    int hi  = nf & 1;
    uint2* base = g_wH + ((size_t)(i * KS + v) * 256) + p * 64 + gid * 8 + hi;
    #pragma unroll
    for (int q = 0; q < 4; q++) {
        __half pk[4] = { h[2*q], h[2*q+1], h[2*q+8], h[2*q+9] };
        base[q * 2] = *(const uint2*)pk;   // [tig=q], stride 2 uint2 = 16B
    }
}

// ---------------- main conv kernel ----------------
__global__ void __launch_bounds__(256, 1)
conv_kernel(const float* __restrict__ bias, float* __restrict__ out)
{
    extern __shared__ __align__(128) char smem[];
    const uint32_t sb = smem_u32(smem);
    const int x0 = blockIdx.x * TXT;
    const int y0 = blockIdx.y * TYT;
    const int b  = blockIdx.z;
    const int tid  = threadIdx.x;
    const int wrp  = tid >> 5;
    const int lane = tid & 31;
    const int gid  = lane >> 2;
    const int tig  = lane & 3;

    auto stage_weights = [&](int it) {
        const uint4* src = (const uint4*)(g_wH + (size_t)it * (KS * 256));
        uint32_t dst = sb + SM_W_OFF + (uint32_t)(it & 1) * WBLKB;
        #pragma unroll 4
        for (int t = tid; t < KS * 128; t += 256)   // 3968 uint4
            cpa16(dst + (uint32_t)t * 16, src + t);
    };
    auto stage_row = [&](int cc, int r) {
        int slot = r % RSL;
        const uint4* src = g_sH +
            ((((size_t)(b * NCC + cc) * YPADN + (size_t)(y0 + r)) * XPADN) + x0) * 2;
        uint32_t dst = sb + (uint32_t)slot * ROWB;
        if (tid < ROWU)
            cpa16(dst + (uint32_t)tid * 16, src + tid);
    };
    auto stage32 = [&](int cc) {
        for (int t = tid; t < 32 * ROWU; t += 256) {
            int r = t / ROWU, c = t - r * ROWU;
            const uint4* src = g_sH +
                ((((size_t)(b * NCC + cc) * YPADN + (size_t)(y0 + r)) * XPADN) + x0) * 2 + c;
            cpa16(sb + (uint32_t)(r % RSL) * ROWB + (uint32_t)c * 16, src);
        }
    };

    stage32(0);
    stage_weights(0);
    cpa_commit();

    float acc[4][8][4];
    #pragma unroll
    for (int mi = 0; mi < 4; mi++)
      #pragma unroll
      for (int nf = 0; nf < 8; nf++)
        #pragma unroll
        for (int r = 0; r < 4; r++)
          acc[mi][nf][r] = 0.f;

    cpa_wait0();
    __syncthreads();

    int cc = 0, u = 0;
    for (int i = 0; i < NITER; i++) {
        bool last = (i == NITER - 1);
        bool bnd  = (u == KS - 1);
        if (!last) {
            if (!bnd) stage_row(cc, u + 32);
            stage_weights(i + 1);
            cpa_commit();
        }

        // ---- compute: B-prefetch pipelined v-loop ----
        {
            const char* rowp[4];
            #pragma unroll
            for (int mi = 0; mi < 4; mi++) {
                int s = wrp * 4 + mi + u;
                if (s >= RSL) s -= RSL;
                rowp[mi] = smem + s * ROWB + tig * 8 + (gid + 1) * 32;
            }
            // paired-B base: [v][p][gid][tig] 16B units
            const char* wb0 = smem + SM_W_OFF + (i & 1) * WBLKB + gid * 64 + tig * 16;

            uint4 cb[4], nb[4];

            #define LOADB4(dst, vv) { \
                const char* wb_ = wb0 + (vv) * 2048; \
                _Pragma("unroll") \
                for (int p = 0; p < 4; p++) \
                    dst[p] = *(const uint4*)(wb_ + p * 512); }
            #define AMMA(bf, vv) { \
                uint2 alo[4], ahi[4]; \
                _Pragma("unroll") \
                for (int mi = 0; mi < 4; mi++) { \
                    const char* ap_ = rowp[mi] + (vv) * 32; \
                    alo[mi] = *(const uint2*)(ap_); \
                    ahi[mi] = *(const uint2*)(ap_ + 256); } \
                _Pragma("unroll") \
                for (int p = 0; p < 4; p++) \
                    _Pragma("unroll") \
                    for (int mi = 0; mi < 4; mi++) { \
                        hmma16(acc[mi][2*p],   alo[mi].x, ahi[mi].x, alo[mi].y, ahi[mi].y, \
                               bf[p].x, bf[p].y); \
                        hmma16(acc[mi][2*p+1], alo[mi].x, ahi[mi].x, alo[mi].y, ahi[mi].y, \
                               bf[p].z, bf[p].w); } }

            LOADB4(cb, 0);
            #pragma unroll 1
            for (int v = 0; v < 30; v += 2) {
                LOADB4(nb, v + 1);
                AMMA(cb, v);
                LOADB4(cb, v + 2);
                AMMA(nb, v + 1);
            }
            AMMA(cb, 30);

            #undef LOADB4
            #undef AMMA
        }

        if (!last) {
            if (!bnd) {
                cpa_wait0();
                __syncthreads();
                u++;
            } else {
                __syncthreads();
                stage32(cc + 1);
                cpa_commit();
                cpa_wait0();
                __syncthreads();
                cc++; u = 0;
            }
        }
    }

    // ---- epilogue ----
    #pragma unroll
    for (int mi = 0; mi < 4; mi++) {
        int y = y0 + wrp * 4 + mi;
        #pragma unroll
        for (int nf = 0; nf < 8; nf++) {
            int on = nf * 8 + tig * 2;
            float bv0 = __ldg(&bias[on]);
            float bv1 = __ldg(&bias[on + 1]);
            int xa = x0 + gid;
            int xb = xa + 8;
            size_t base0 = ((size_t)(b * C_OUT + on) * HW + y) * HW;
            size_t base1 = ((size_t)(b * C_OUT + on + 1) * HW + y) * HW;
            out[base0 + xa] = acc[mi][nf][0] + bv0;
            out[base1 + xa] = acc[mi][nf][1] + bv1;
            out[base0 + xb] = acc[mi][nf][2] + bv0;
            out[base1 + xb] = acc[mi][nf][3] + bv1;
        }
    }
}

// ---------------- launch ----------------
extern "C" void kernel_launch(void* const* d_in, const int* in_sizes, int n_in,
                              void* d_out, int out_size) {
    const float* sig  = (const float*)d_in[0];
    const float* wgt  = (const float*)d_in[1];
    const float* bias = (const float*)d_in[2];
    float* out = (float*)d_out;

    static bool attr_set = false;
    if (!attr_set) {
        cudaFuncSetAttribute(conv_kernel, cudaFuncAttributeMaxDynamicSharedMemorySize,
                             SMEM_TOTAL);
        attr_set = true;
    }

    {
        const size_t total = (size_t)B_N * NCC * YPADN * XPADN;
        prep_sig<<<(unsigned)((total + 255) / 256), 256>>>(sig);
    }
    {
        const size_t total = (size_t)NITER * KS * C_OUT;
        prep_w<<<(unsigned)((total + 255) / 256), 256>>>(wgt);
    }
    dim3 grid(HW / TXT, HW / TYT, B_N);
    conv_kernel<<<grid, 256, SMEM_TOTAL>>>(bias, out);
}